// round 16
// baseline (speedup 1.0000x reference)
#include <cuda_runtime.h>
#include <cuda_fp16.h>
#include <cstdint>

#define BB 8
#define SS 4096
#define DD 256
#define NROWS (BB*SS)
#define NEGV  (-1000000000.0f)
#define NSPLIT 8
#define KSPLIT (SS/NSPLIT)   // 512
#define NCH1 (KSPLIT/64)     // 8  (64-row chunks)
#define NCH2 (DD/64)         // 4
#define P1 272               // pitch: 128 fp16 cols + pad
#define P2N 144              // pitch: 64 fp16 cols + pad (g2 A)
#define ASZ1 (64*P1)         // 17408
#define BUF1 (2*ASZ1)        // 34816  (A,B) -- g1
#define A2SZ (128*P2N)       // 18432
#define B2SZ (64*P1)         // 17408
#define BUF2 (A2SZ + B2SZ)   // 35840  -- g2

// ---- scratch ----
__device__ __half g_kh[NROWS*DD];        // fp16 K * 256/||k||^2
__device__ float  g_s1p[NSPLIT][BB*DD*DD];
__device__ __half g_s1h[BB*DD*DD];       // fp16 s1_true
__device__ int    g_mask_kind;

// ============================ helpers ============================
__device__ __forceinline__ uint32_t smem_u32(const void* p) {
    uint32_t a;
    asm("{ .reg .u64 t; cvta.to.shared.u64 t, %1; cvt.u32.u64 %0, t; }"
        : "=r"(a) : "l"(p));
    return a;
}
__device__ __forceinline__ void ldsm_x4(uint32_t* r, uint32_t a) {
    asm volatile("ldmatrix.sync.aligned.m8n8.x4.shared.b16 {%0,%1,%2,%3}, [%4];"
        : "=r"(r[0]), "=r"(r[1]), "=r"(r[2]), "=r"(r[3]) : "r"(a));
}
__device__ __forceinline__ void ldsm_x4t(uint32_t* r, uint32_t a) {
    asm volatile("ldmatrix.sync.aligned.m8n8.x4.trans.shared.b16 {%0,%1,%2,%3}, [%4];"
        : "=r"(r[0]), "=r"(r[1]), "=r"(r[2]), "=r"(r[3]) : "r"(a));
}
__device__ __forceinline__ void mma_f16(float* c, const uint32_t* a, const uint32_t* b) {
    asm volatile(
        "mma.sync.aligned.m16n8k16.row.col.f32.f16.f16.f32 "
        "{%0,%1,%2,%3}, {%4,%5,%6,%7}, {%8,%9}, {%0,%1,%2,%3};"
        : "+f"(c[0]), "+f"(c[1]), "+f"(c[2]), "+f"(c[3])
        : "r"(a[0]), "r"(a[1]), "r"(a[2]), "r"(a[3]), "r"(b[0]), "r"(b[1]));
}
__device__ __forceinline__ uint32_t pack_h(float x0, float x1) {
    __half2 hh = __floats2half2_rn(x0, x1);
    return *reinterpret_cast<uint32_t*>(&hh);
}
__device__ __forceinline__ bool is_masked(const void* mask, int row) {
    int kind = g_mask_kind;
    if (kind == 1) return ((const unsigned char*)mask)[row] != 0;
    if (kind == 2) return ((const float*)mask)[row] != 0.0f;
    return ((const int*)mask)[row] != 0;
}

// ============================ Kernel 1: K norms -> Kh fp16; (block 0) mask sniff ============================
__global__ void k_knorm(const float* __restrict__ k, const unsigned int* __restrict__ m) {
    if (blockIdx.x == 0) {
        __shared__ int s_u8, s_f;
        if (threadIdx.x == 0) { s_u8 = 0; s_f = 0; }
        __syncthreads();
        for (int i = threadIdx.x; i < 8192; i += 256) {
            unsigned v = m[i];
            if (v == 0x3F800000u)      s_f  = 1;
            else if (v > 1u)           s_u8 = 1;
        }
        __syncthreads();
        if (threadIdx.x == 0) g_mask_kind = s_u8 ? 1 : (s_f ? 2 : 0);
    }
    int row  = blockIdx.x * 8 + (threadIdx.x >> 5);
    int lane = threadIdx.x & 31;
    const float4* k4 = (const float4*)(k + (size_t)row * DD);
    float4 b0 = k4[lane], b1 = k4[lane + 32];
    float sb = b0.x*b0.x + b0.y*b0.y + b0.z*b0.z + b0.w*b0.w
             + b1.x*b1.x + b1.y*b1.y + b1.z*b1.z + b1.w*b1.w;
#pragma unroll
    for (int o = 16; o; o >>= 1) sb += __shfl_xor_sync(0xFFFFFFFFu, sb, o);
    const float ib = 256.0f / sb;
    __half* kh = g_kh + (size_t)row * DD;
    *(uint2*)(kh + lane * 4)       = make_uint2(pack_h(b0.x*ib, b0.y*ib), pack_h(b0.z*ib, b0.w*ib));
    *(uint2*)(kh + 128 + lane * 4) = make_uint2(pack_h(b1.x*ib, b1.y*ib), pack_h(b1.z*ib, b1.w*ib));
}

// ============================ Kernel 2: GEMM1 (64-k chunks, substaged loads) ============================
__global__ void __launch_bounds__(256, 2)
k_g1(const float* __restrict__ V) {
    extern __shared__ __align__(16) char sm[];
    const uint32_t sb = smem_u32(sm);
    const int tid = threadIdx.x, lane = tid & 31, wid = tid >> 5;
    const int b = blockIdx.z, split = blockIdx.y;
    const int m0 = (blockIdx.x >> 1) * 128, n0 = (blockIdx.x & 1) * 128;
    const __half* KhB = g_kh + (size_t)b * SS * DD;
    const float*  Vb  = V + (size_t)b * SS * DD;

    const int sl = tid >> 3, q0 = tid & 7;            // 32 rows per substage
    const int wm = (wid >> 2) * 64, wn = (wid & 3) * 32;
    const int rowT = (lane & 7) + ((lane >> 4) << 3);
    const int colT = ((lane >> 3) & 1) << 3;
    const int rowB = lane & 15;
    const int colB = (lane >> 4) << 3;

    float acc[4][4][4];
#pragma unroll
    for (int i = 0; i < 4; i++)
#pragma unroll
        for (int j = 0; j < 4; j++)
#pragma unroll
            for (int t = 0; t < 4; t++) acc[i][j][t] = 0.f;

    uint2 ra[4]; float4 rv[4];
    auto ldSub = [&](int c, int h) {
        int s = split * KSPLIT + c * 64 + h * 32 + sl;
        const __half* kr = KhB + (size_t)s * DD + m0;
        const float*  vr = Vb + (size_t)s * DD + n0;
#pragma unroll
        for (int j = 0; j < 4; j++) {
            ra[j] = *(const uint2*)(kr + 4 * (q0 + 8 * j));
            rv[j] = *(const float4*)(vr + 4 * (q0 + 8 * j));
        }
    };
    auto stSub = [&](int bi, int h) {
        char* Ah = sm + bi * BUF1;
        char* Bh = Ah + ASZ1;
        int r = h * 32 + sl;
#pragma unroll
        for (int j = 0; j < 4; j++) {
            int off = r * P1 + 8 * (q0 + 8 * j);
            *(uint2*)(Ah + off) = ra[j];
            *(uint2*)(Bh + off) = make_uint2(pack_h(rv[j].x, rv[j].y),
                                             pack_h(rv[j].z, rv[j].w));
        }
    };
    auto mmaHalf = [&](uint32_t ub, int ksBase) {
        const uint32_t uAh = ub, uBh = ub + ASZ1;
#pragma unroll
        for (int kk = 0; kk < 2; kk++) {
            int ks = ksBase + kk * 16;
            uint32_t ah[4][4], bh[4][2];
#pragma unroll
            for (int mf = 0; mf < 4; mf++) {
                uint32_t a = (uint32_t)((ks + rowT) * P1 + 2 * (wm + mf * 16 + colT));
                ldsm_x4t(ah[mf], uAh + a);
            }
#pragma unroll
            for (int nb2 = 0; nb2 < 2; nb2++) {
                uint32_t a = (uint32_t)((ks + rowB) * P1 + 2 * (wn + nb2 * 16 + colB));
                ldsm_x4t(&bh[nb2 * 2][0], uBh + a);
            }
#pragma unroll
            for (int mi = 0; mi < 4; mi++)
#pragma unroll
                for (int ni = 0; ni < 4; ni++)
                    mma_f16(acc[mi][ni], ah[mi], bh[ni]);
        }
    };

    // prologue: chunk 0 -> buf0
    ldSub(0, 0); stSub(0, 0);
    ldSub(0, 1); stSub(0, 1);
    __syncthreads();

    for (int c = 0; c < NCH1; c++) {
        const uint32_t ub = sb + (uint32_t)(c & 1) * BUF1;
        const int nb = (c + 1) & 1;
        if (c + 1 < NCH1) ldSub(c + 1, 0);
        mmaHalf(ub, 0);
        if (c + 1 < NCH1) { stSub(nb, 0); ldSub(c + 1, 1); }
        mmaHalf(ub, 32);
        if (c + 1 < NCH1) stSub(nb, 1);
        __syncthreads();
    }

    float* out = g_s1p[split] + (size_t)b * DD * DD;
    const int r0 = lane >> 2, cp = (lane & 3) * 2;
#pragma unroll
    for (int mi = 0; mi < 4; mi++)
#pragma unroll
        for (int ni = 0; ni < 4; ni++) {
            int m = m0 + wm + mi * 16 + r0;
            int n = n0 + wn + ni * 8 + cp;
            *(float2*)(out + (size_t)m * DD + n)       = make_float2(acc[mi][ni][0], acc[mi][ni][1]);
            *(float2*)(out + (size_t)(m + 8) * DD + n) = make_float2(acc[mi][ni][2], acc[mi][ni][3]);
        }
}

// ============================ Kernel 3: reduce 8 partials -> fp16 s1_true ============================
__global__ void k_reduce() {   // grid (32 dchunks, 8 b), 256 thr (e)
    const int b = blockIdx.y, dc = blockIdx.x, e = threadIdx.x;
    const float r = 1.0f / 256.0f;
    size_t base = ((size_t)b * DD + dc * 8) * DD + e;
#pragma unroll
    for (int d8 = 0; d8 < 8; d8++) {
        size_t idx = base + (size_t)d8 * DD;
        float s = 0.f;
#pragma unroll
        for (int p = 0; p < NSPLIT; p++) s += g_s1p[p][idx];
        g_s1h[idx] = __float2half(s * r);   // s1_true
    }
}

// ============================ Kernel 4: GEMM2 (64-k chunks, substaged loads) ============================
__global__ void __launch_bounds__(256, 2)
k_g2(const float* __restrict__ Q, const void* __restrict__ mask,
     float* __restrict__ Out) {
    extern __shared__ __align__(16) char sm[];
    const uint32_t sb = smem_u32(sm);
    const int tid = threadIdx.x, lane = tid & 31, wid = tid >> 5;
    const int b = blockIdx.z, m0 = blockIdx.y * 128, n0 = blockIdx.x * 128;
    const float*  Qb  = Q + (size_t)b * SS * DD;
    const __half* s1b = g_s1h + (size_t)b * DD * DD;
    float* smul = (float*)(sm + 2 * BUF2);

    const int ar = tid >> 1, aq0 = tid & 1;    // A: 2 thr/row, 128 rows; 32-k substage
    const int blr = tid >> 3, bq0 = tid & 7;   // B: 8 thr/row, 32 rows per substage
    const int wm = (wid >> 2) * 64, wn = (wid & 3) * 32;
    const int rowA = lane & 15, colA = (lane >> 4) << 3;
    const int rowB = lane & 15, colB = (lane >> 4) << 3;

    float acc[4][4][4];
#pragma unroll
    for (int i = 0; i < 4; i++)
#pragma unroll
        for (int j = 0; j < 4; j++)
#pragma unroll
            for (int t = 0; t < 4; t++) acc[i][j][t] = 0.f;

    const bool msk = is_masked(mask, b * SS + m0 + ar);
    float qss = 0.f;
    float4 ra[4]; uint2 rb[4];
    auto ldSub = [&](int c, int h) {
        const float* qr = Qb + (size_t)(m0 + ar) * DD + c * 64 + h * 32;
#pragma unroll
        for (int j = 0; j < 4; j++) {
            ra[j] = *(const float4*)(qr + 4 * (aq0 + 2 * j));
            qss += ra[j].x*ra[j].x + ra[j].y*ra[j].y + ra[j].z*ra[j].z + ra[j].w*ra[j].w;
            if (msk) ra[j] = make_float4(1.f, 1.f, 1.f, 1.f);
            int kl = c * 64 + h * 32 + blr;
            rb[j] = *(const uint2*)(s1b + (size_t)kl * DD + n0 + 4 * (bq0 + 8 * j));
        }
    };
    auto stSub = [&](int bi, int h) {
        char* Ah = sm + bi * BUF2;
        char* Bh = Ah + A2SZ;
#pragma unroll
        for (int j = 0; j < 4; j++) {
            int off = ar * P2N + h * 64 + 8 * (aq0 + 2 * j);
            *(uint2*)(Ah + off) = make_uint2(pack_h(ra[j].x, ra[j].y),
                                             pack_h(ra[j].z, ra[j].w));
            int offb = (h * 32 + blr) * P1 + 8 * (bq0 + 8 * j);
            *(uint2*)(Bh + offb) = rb[j];
        }
    };
    auto mmaHalf = [&](uint32_t ub, int ksBase) {
        const uint32_t uAh = ub, uBh = ub + A2SZ;
#pragma unroll
        for (int kk = 0; kk < 2; kk++) {
            int ks = ksBase + kk * 16;
            uint32_t ah[4][4], bh[4][2];
#pragma unroll
            for (int mf = 0; mf < 4; mf++) {
                uint32_t a = (uint32_t)((wm + mf * 16 + rowA) * P2N + 2 * (ks + colA));
                ldsm_x4(ah[mf], uAh + a);
            }
#pragma unroll
            for (int nb2 = 0; nb2 < 2; nb2++) {
                uint32_t a = (uint32_t)((ks + rowB) * P1 + 2 * (wn + nb2 * 16 + colB));
                ldsm_x4t(&bh[nb2 * 2][0], uBh + a);
            }
#pragma unroll
            for (int mi = 0; mi < 4; mi++)
#pragma unroll
                for (int ni = 0; ni < 4; ni++)
                    mma_f16(acc[mi][ni], ah[mi], bh[ni]);
        }
    };

    // prologue: chunk 0 -> buf0
    ldSub(0, 0); stSub(0, 0);
    ldSub(0, 1); stSub(0, 1);
    __syncthreads();

    for (int c = 0; c < NCH2; c++) {
        const uint32_t ub = sb + (uint32_t)(c & 1) * BUF2;
        const int nb = (c + 1) & 1;
        if (c + 1 < NCH2) ldSub(c + 1, 0);
        mmaHalf(ub, 0);
        if (c + 1 < NCH2) { stSub(nb, 0); ldSub(c + 1, 1); }
        mmaHalf(ub, 32);
        if (c + 1 < NCH2) stSub(nb, 1);
        __syncthreads();
    }

    qss += __shfl_xor_sync(0xFFFFFFFFu, qss, 1);
    if (aq0 == 0) smul[ar] = msk ? 0.0f : 1.0f / qss;
    __syncthreads();

    const float sc = 1.0f / 256.0f;
    const int r0 = lane >> 2, cp = (lane & 3) * 2;
#pragma unroll
    for (int mi = 0; mi < 4; mi++) {
        int m1 = m0 + wm + mi * 16 + r0;
        int m2 = m1 + 8;
        float mu1 = smul[m1 - m0], mu2 = smul[m2 - m0];
        float s1f = (mu1 == 0.0f) ? (NEGV * sc) : mu1 * sc;
        float s2f = (mu2 == 0.0f) ? (NEGV * sc) : mu2 * sc;
        float* o1 = Out + ((size_t)b * SS + m1) * DD;
        float* o2 = Out + ((size_t)b * SS + m2) * DD;
#pragma unroll
        for (int ni = 0; ni < 4; ni++) {
            int n = n0 + wn + ni * 8 + cp;
            *(float2*)(o1 + n) = make_float2(acc[mi][ni][0] * s1f, acc[mi][ni][1] * s1f);
            *(float2*)(o2 + n) = make_float2(acc[mi][ni][2] * s2f, acc[mi][ni][3] * s2f);
        }
    }
}

// ===========================================================================
extern "C" void kernel_launch(void* const* d_in, const int* in_sizes, int n_in,
                              void* d_out, int out_size) {
    const float* q    = (const float*)d_in[0];
    const float* k    = (const float*)d_in[1];
    const float* v    = (const float*)d_in[2];
    const void*  mask = d_in[3];
    float* out = (float*)d_out;

    const int SMEM_G1 = 2 * BUF1;          // 69632
    const int SMEM_G2 = 2 * BUF2 + 512;    // 72192
    cudaFuncSetAttribute(k_g1, cudaFuncAttributeMaxDynamicSharedMemorySize, SMEM_G1);
    cudaFuncSetAttribute(k_g2, cudaFuncAttributeMaxDynamicSharedMemorySize, SMEM_G2);

    k_knorm<<<NROWS / 8, 256>>>(k, (const unsigned int*)mask);
    k_g1<<<dim3(4, NSPLIT, BB), 256, SMEM_G1>>>(v);
    k_reduce<<<dim3(32, 8), 256>>>();
    k_g2<<<dim3(2, SS / 128, BB), 256, SMEM_G2>>>(q, mask, out);
}